// round 5
// baseline (speedup 1.0000x reference)
#include <cuda_runtime.h>
#include <cuda_bf16.h>

// Scratch (allocation-free rule: __device__ globals).
#define MAX_S 262144
#define MAX_N 2097152
__device__ int      g_count[MAX_S];
__device__ int      g_base[MAX_S];
__device__ int      g_cursor[MAX_S];
__device__ int      g_bsum[1024];
__device__ unsigned g_last[MAX_S];    // bit pattern of segment-max timestamp (all t > 0)
__device__ int      g_perm[MAX_N];    // row indices grouped by segment
__device__ float    g_wval[MAX_N];    // per-row decay weight, same ordering as g_perm

#define BETA 0.8f
#define SCAN_B 1024

// ---------------------------------------------------------------------------
__global__ void twma_init_kernel(int S) {
    int i = blockIdx.x * blockDim.x + threadIdx.x;
    if (i < S) {
        g_count[i] = 0;
        g_last[i]  = 0u;
    }
}

// Histogram of segment ids + segment-max of timestamps (uint order == float
// order since all t > 0; init 0 => empty segments output last_t = 0, matching
// the reference's where(tw>0, last_t, 0)).
__global__ void twma_hist_kernel(const int* __restrict__ ids,
                                 const float* __restrict__ ts,
                                 int N) {
    int i = blockIdx.x * blockDim.x + threadIdx.x;
    if (i < N) {
        int s = ids[i];
        atomicAdd(&g_count[s], 1);
        atomicMax(&g_last[s], __float_as_uint(ts[i]));
    }
}

// ---------------------------------------------------------------------------
// Exclusive scan of g_count -> g_base (3 kernels).
__global__ void twma_scan1_kernel(int S) {
    __shared__ int sh[SCAN_B];
    int tid = threadIdx.x;
    int gid = blockIdx.x * SCAN_B + tid;
    int v = (gid < S) ? g_count[gid] : 0;
    sh[tid] = v;
    __syncthreads();
    for (int off = 1; off < SCAN_B; off <<= 1) {
        int t = (tid >= off) ? sh[tid - off] : 0;
        __syncthreads();
        sh[tid] += t;
        __syncthreads();
    }
    int incl = sh[tid];
    if (gid < S) g_base[gid] = incl - v;          // exclusive
    if (tid == SCAN_B - 1) g_bsum[blockIdx.x] = incl;
}

// Small scan of the <=64 block sums: 64 threads, cheap ladder.
__global__ void twma_scan2_kernel(int nb) {
    __shared__ int sh[64];
    int tid = threadIdx.x;
    int v = (tid < nb) ? g_bsum[tid] : 0;
    sh[tid] = v;
    __syncthreads();
    for (int off = 1; off < 64; off <<= 1) {
        int t = (tid >= off) ? sh[tid - off] : 0;
        __syncthreads();
        sh[tid] += t;
        __syncthreads();
    }
    if (tid < nb) g_bsum[tid] = sh[tid] - v;      // exclusive
}

__global__ void twma_scan3_kernel(int S) {
    int gid = blockIdx.x * SCAN_B + threadIdx.x;
    if (gid < S) {
        int b = g_base[gid] + g_bsum[blockIdx.x];
        g_base[gid]   = b;
        g_cursor[gid] = b;
    }
}

// ---------------------------------------------------------------------------
// Bucket rows by segment AND precompute the decay weight per row (last_t is
// final by this point). Removes the dependent ts-load + exp from the gather's
// hot loop.
__global__ void twma_scatter_kernel(const int*   __restrict__ ids,
                                    const float* __restrict__ ts,
                                    int N) {
    int i = blockIdx.x * blockDim.x + threadIdx.x;
    if (i < N) {
        int   s  = ids[i];
        float lt = __uint_as_float(g_last[s]);
        float w  = __expf(BETA * (ts[i] - lt));   // w in (0, 1]
        int p = atomicAdd(&g_cursor[s], 1);
        g_perm[p] = i;
        g_wval[p] = w;
    }
}

// ---------------------------------------------------------------------------
// One warp per segment: gather the segment's rows (full D floats per row,
// NC float4 chunks of 32 lanes each), accumulate w*m in registers, write
// agg = acc/tw and last_t exactly once. Inner loop: contiguous broadcast
// loads of perm/wval + up to NC independent float4 gathers per lane.
__global__ void twma_seg_kernel(const float4* __restrict__ msg,
                                float* __restrict__ out,
                                int S, int C /* D/4 */, int D) {
    int seg  = (blockIdx.x * blockDim.x + threadIdx.x) >> 5;
    if (seg >= S) return;
    int lane = threadIdx.x & 31;
    int nc   = C >> 5;                        // float4 chunks per row (2 for D=256)

    int      base = g_base[seg];
    int      cnt  = g_count[seg];
    unsigned lb   = g_last[seg];

    float4 acc[4];
    #pragma unroll
    for (int j = 0; j < 4; j++) acc[j] = make_float4(0.f, 0.f, 0.f, 0.f);
    float tw = 0.f;

    #pragma unroll 4
    for (int r = 0; r < cnt; r++) {
        int   i = g_perm[base + r];           // broadcast (contiguous across r)
        float w = g_wval[base + r];           // broadcast
        tw += w;
        const float4* row = msg + (long long)i * C + lane;
        #pragma unroll
        for (int j = 0; j < 4; j++) {
            if (j < nc) {
                float4 m = row[j * 32];
                acc[j].x += w * m.x;
                acc[j].y += w * m.y;
                acc[j].z += w * m.z;
                acc[j].w += w * m.w;
            }
        }
    }

    float inv = (cnt > 0) ? (1.0f / tw) : 0.0f;
    float4* dst = reinterpret_cast<float4*>(out) + (long long)seg * C + lane;
    #pragma unroll
    for (int j = 0; j < 4; j++) {
        if (j < nc) {
            dst[j * 32] = make_float4(acc[j].x * inv, acc[j].y * inv,
                                      acc[j].z * inv, acc[j].w * inv);
        }
    }

    if (lane == 0) {
        out[(long long)S * D + seg] = __uint_as_float(lb);  // 0 for empty segs
    }
}

// ---------------------------------------------------------------------------
extern "C" void kernel_launch(void* const* d_in, const int* in_sizes, int n_in,
                              void* d_out, int out_size) {
    const float* msg = (const float*)d_in[0];   // [N, D] fp32
    const float* ts  = (const float*)d_in[1];   // [N]    fp32
    const int*   ids = (const int*)d_in[2];     // [N]    int32

    int N = in_sizes[1];
    int D = in_sizes[0] / N;          // 256
    int S = out_size / (D + 1);       // 65536 (out = S*D agg + S last_t)
    int C = D / 4;

    float* out = (float*)d_out;

    twma_init_kernel<<<(S + 255) / 256, 256>>>(S);
    twma_hist_kernel<<<(N + 255) / 256, 256>>>(ids, ts, N);

    int nb = (S + SCAN_B - 1) / SCAN_B;         // 64 for S=65536 (<=64 assumed)
    twma_scan1_kernel<<<nb, SCAN_B>>>(S);
    twma_scan2_kernel<<<1, 64>>>(nb);
    twma_scan3_kernel<<<nb, SCAN_B>>>(S);

    twma_scatter_kernel<<<(N + 255) / 256, 256>>>(ids, ts, N);

    long long threads = (long long)S * 32;      // one warp per segment
    unsigned blocks = (unsigned)((threads + 255) / 256);
    twma_seg_kernel<<<blocks, 256>>>((const float4*)msg, out, S, C, D);
}